// round 3
// baseline (speedup 1.0000x reference)
#include <cuda_runtime.h>
#include <cstdint>
#include <math.h>

// Problem constants
#define N_NODES 8192
#define IN_C    128
#define OUT_C   16
// K hops = 3 adjacency matrices

// ---------------------------------------------------------------------------
// Scratch: support = X @ W + b   [8192 x 16]  (512 KB, __device__ global)
// ---------------------------------------------------------------------------
__device__ float g_support[N_NODES * OUT_C];

// ---------------------------------------------------------------------------
// Helpers: packed f32x2 math (Blackwell PTX), cp.async, smem addr
// ---------------------------------------------------------------------------
__device__ __forceinline__ unsigned long long pack2(uint32_t a, uint32_t b) {
    unsigned long long r;
    asm("mov.b64 %0, {%1,%2};" : "=l"(r) : "r"(a), "r"(b));
    return r;
}
#define FMA_F32X2(d, a, b, c) \
    asm("fma.rn.f32x2 %0, %1, %2, %3;" : "=l"(d) : "l"(a), "l"(b), "l"(c))
#define ADD_F32X2(d, a, b) \
    asm("add.rn.f32x2 %0, %1, %2;" : "=l"(d) : "l"(a), "l"(b))
#define UNPACK_F32X2(lo, hi, v) \
    asm("mov.b64 {%0,%1}, %2;" : "=r"(lo), "=r"(hi) : "l"(v))

__device__ __forceinline__ uint32_t smem_u32(const void* p) {
    uint32_t a;
    asm("{ .reg .u64 t; cvta.to.shared.u64 t, %1; cvt.u32.u64 %0, t; }"
        : "=r"(a) : "l"(p));
    return a;
}
#define CP_ASYNC16(dst, src) \
    asm volatile("cp.async.cg.shared.global [%0], [%1], 16;" :: "r"(dst), "l"(src))
#define CP_COMMIT()  asm volatile("cp.async.commit_group;")
#define CP_WAIT2()   asm volatile("cp.async.wait_group 2;" ::: "memory")
#define CP_WAIT1()   asm volatile("cp.async.wait_group 1;" ::: "memory")
#define CP_WAIT0()   asm volatile("cp.async.wait_group 0;" ::: "memory")

// ---------------------------------------------------------------------------
// Kernel 1: support[m][d] = sum_c x[m][c]*w[c][d] + b[d]
// ---------------------------------------------------------------------------
__global__ void __launch_bounds__(256) support_kernel(
    const float* __restrict__ x, const float* __restrict__ w,
    const float* __restrict__ b)
{
    __shared__ float ws[IN_C * OUT_C];   // 8 KB
    int t = threadIdx.x;
    #pragma unroll
    for (int i = t; i < IN_C * OUT_C; i += 256) ws[i] = w[i];
    __syncthreads();

    int d = t & 15;
    int m = blockIdx.x * 16 + (t >> 4);
    float acc = b[d];
    const float4* xr = (const float4*)(x + (long)m * IN_C);
    #pragma unroll
    for (int c4 = 0; c4 < IN_C / 4; c4++) {
        float4 xv = xr[c4];
        int c = c4 * 4;
        acc = fmaf(xv.x, ws[(c + 0) * 16 + d], acc);
        acc = fmaf(xv.y, ws[(c + 1) * 16 + d], acc);
        acc = fmaf(xv.z, ws[(c + 2) * 16 + d], acc);
        acc = fmaf(xv.w, ws[(c + 3) * 16 + d], acc);
    }
    g_support[m * OUT_C + d] = acc;
}

// ---------------------------------------------------------------------------
// Kernel 2: out[n][d] = sum_m (att0*adj0+att1*adj1+att2*adj2)[n][m] * S[m][d]
//
// WARP-PRIVATE pipeline: each of 8 warps owns 4 rows and streams its own adj
// slice (3 mats x 4 rows x 64 floats = 3 KB/tile) through a 4-stage
// warp-private cp.async ring. NO __syncthreads in the main loop — only
// per-thread wait_group + __syncwarp. Support is read via __ldg (L2/L1-hot).
// smem: 8 warps * 4 stages * 3 KB = 96 KB/CTA, 2 CTAs/SM = 192 KB.
// ---------------------------------------------------------------------------
#define MT           64
#define ROWS         32
#define WARP_TILE    (3 * 4 * MT)                 // 768 floats = 3 KB
#define STAGES       4
#define SMEM_BYTES   (8 * STAGES * WARP_TILE * 4) // 98304

__device__ __forceinline__ void issue_warp_tile(
    uint32_t dst, const float* __restrict__ adj,
    int row0, int tile, int lane)
{
    long t0 = (long)tile * MT;
    // 3 mats * 4 rows * 16 chunks(16B) = 192 chunks -> 6 per lane
    #pragma unroll
    for (int i = 0; i < 6; i++) {
        int c   = lane + i * 32;
        int k   = c >> 6;         // /64: matrix 0..2
        int rem = c & 63;
        int r   = rem >> 4;       // row 0..3
        int j   = rem & 15;       // 16B chunk 0..15
        const float* src = adj + (long)k * N_NODES * N_NODES
                               + (long)(row0 + r) * N_NODES + t0 + j * 4;
        CP_ASYNC16(dst + (uint32_t)((k * (4 * MT) + r * MT + j * 4) * 4), src);
    }
    CP_COMMIT();
}

__global__ void __launch_bounds__(256, 2) gcn_main_kernel(
    const float* __restrict__ adj, const float* __restrict__ attp,
    float* __restrict__ out)
{
    extern __shared__ float sm[];
    const int NTILES = N_NODES / MT;   // 128
    int tid  = threadIdx.x;
    int warp = tid >> 5;
    int lane = tid & 31;
    int n0   = blockIdx.x * ROWS;
    int row0 = n0 + warp * 4;

    float* wbuf = sm + warp * (STAGES * WARP_TILE);
    uint32_t wbuf_u32 = smem_u32(wbuf);

    // softmax over the 3 attention params
    float p0 = __ldg(attp), p1 = __ldg(attp + 1), p2 = __ldg(attp + 2);
    float mx = fmaxf(p0, fmaxf(p1, p2));
    float e0 = expf(p0 - mx), e1 = expf(p1 - mx), e2 = expf(p2 - mx);
    float inv = 1.0f / (e0 + e1 + e2);
    float att0 = e0 * inv, att1 = e1 * inv, att2 = e2 * inv;

    unsigned long long acc[4][8];
    #pragma unroll
    for (int r = 0; r < 4; r++)
        #pragma unroll
        for (int j = 0; j < 8; j++) acc[r][j] = 0ull;

    const float4* gs = (const float4*)g_support;

    // Prologue: fill stages 0..2 (3 groups in flight)
    issue_warp_tile(wbuf_u32 + 0 * WARP_TILE * 4, adj, row0, 0, lane);
    issue_warp_tile(wbuf_u32 + 1 * WARP_TILE * 4, adj, row0, 1, lane);
    issue_warp_tile(wbuf_u32 + 2 * WARP_TILE * 4, adj, row0, 2, lane);

    for (int t = 0; t < NTILES; t++) {
        // Wait until tile t's group has landed (per-thread), then warp-sync.
        int remaining = NTILES - 1 - t;   // groups issued after tile t
        if (remaining >= 2)      { CP_WAIT2(); }
        else if (remaining == 1) { CP_WAIT1(); }
        else                     { CP_WAIT0(); }
        __syncwarp();

        // Refill: stage (t+3)%4 was consumed at iteration t-1 -> free.
        if (t + 3 < NTILES) {
            issue_warp_tile(wbuf_u32 + ((t + 3) & 3) * WARP_TILE * 4,
                            adj, row0, t + 3, lane);
        }

        const float* A = wbuf + (t & 3) * WARP_TILE;
        long t0 = (long)t * MT;

        #pragma unroll
        for (int step = 0; step < MT / 32; step++) {
            int m = step * 32 + lane;
            // support row (t0+m): 4 float4 via read-only cache (L1/L2 hot)
            long sbase = (t0 + m) * (OUT_C / 4);
            float4 q0 = __ldg(gs + sbase + 0);
            float4 q1 = __ldg(gs + sbase + 1);
            float4 q2 = __ldg(gs + sbase + 2);
            float4 q3 = __ldg(gs + sbase + 3);
            unsigned long long p[8];
            p[0] = pack2(__float_as_uint(q0.x), __float_as_uint(q0.y));
            p[1] = pack2(__float_as_uint(q0.z), __float_as_uint(q0.w));
            p[2] = pack2(__float_as_uint(q1.x), __float_as_uint(q1.y));
            p[3] = pack2(__float_as_uint(q1.z), __float_as_uint(q1.w));
            p[4] = pack2(__float_as_uint(q2.x), __float_as_uint(q2.y));
            p[5] = pack2(__float_as_uint(q2.z), __float_as_uint(q2.w));
            p[6] = pack2(__float_as_uint(q3.x), __float_as_uint(q3.y));
            p[7] = pack2(__float_as_uint(q3.z), __float_as_uint(q3.w));
            #pragma unroll
            for (int r = 0; r < 4; r++) {
                float a0 = A[            r * MT + m];
                float a1 = A[4 * MT    + r * MT + m];
                float a2 = A[8 * MT    + r * MT + m];
                float a  = fmaf(att2, a2, fmaf(att1, a1, att0 * a0));
                unsigned long long aa =
                    pack2(__float_as_uint(a), __float_as_uint(a));
                #pragma unroll
                for (int j = 0; j < 8; j++)
                    FMA_F32X2(acc[r][j], aa, p[j], acc[r][j]);
            }
        }
    }

    // warp-reduce across lanes (m-partition) and store 4 rows * 16 outputs
    #pragma unroll
    for (int r = 0; r < 4; r++) {
        #pragma unroll
        for (int j = 0; j < 8; j++) {
            unsigned long long v = acc[r][j];
            #pragma unroll
            for (int off = 16; off; off >>= 1) {
                unsigned long long o = __shfl_xor_sync(0xffffffffu, v, off);
                ADD_F32X2(v, v, o);
            }
            acc[r][j] = v;
        }
        if (lane == 0) {
            int row = row0 + r;
            float2* o = (float2*)(out + (long)row * OUT_C);
            #pragma unroll
            for (int j = 0; j < 8; j++) {
                uint32_t lo, hi;
                UNPACK_F32X2(lo, hi, acc[r][j]);
                o[j] = make_float2(__uint_as_float(lo), __uint_as_float(hi));
            }
        }
    }
}

// ---------------------------------------------------------------------------
// Launch
// ---------------------------------------------------------------------------
extern "C" void kernel_launch(void* const* d_in, const int* in_sizes, int n_in,
                              void* d_out, int out_size)
{
    const float *x = nullptr, *w = nullptr, *b = nullptr,
                *adj = nullptr, *attp = nullptr;
    for (int i = 0; i < n_in; i++) {
        switch (in_sizes[i]) {
            case N_NODES * IN_C: x    = (const float*)d_in[i]; break;
            case IN_C * OUT_C:   w    = (const float*)d_in[i]; break;
            case OUT_C:          b    = (const float*)d_in[i]; break;
            case 3:              attp = (const float*)d_in[i]; break;
            default:             adj  = (const float*)d_in[i]; break; // 3*8192*8192
        }
    }

    support_kernel<<<N_NODES / 16, 256>>>(x, w, b);

    cudaFuncSetAttribute(gcn_main_kernel,
                         cudaFuncAttributeMaxDynamicSharedMemorySize, SMEM_BYTES);
    gcn_main_kernel<<<N_NODES / ROWS, 256, SMEM_BYTES>>>(adj, attp, (float*)d_out);
}